// round 4
// baseline (speedup 1.0000x reference)
#include <cuda_runtime.h>

// CRF NLL: B=1024, T=512, C=53, BOS=1, EOS=2
// One block (64 thr = 2 warps) per batch; one output column per thread.
// Scaled-prob forward recurrence, packed f32x2 FMA, double-buffered p in smem,
// 4-step emission prefetch, renorm every 4 steps, fused last-block reduction.

#define Bn   1024
#define Tn   512
#define Cn   53
#define BOSi 1
#define EOSi 2

__device__ float    g_partial[Bn];
__device__ unsigned g_ticket;   // zero-init; reset by last block each launch

typedef unsigned long long ull;

__device__ __forceinline__ ull pack2(float a, float b) {
    ull r; asm("mov.b64 %0, {%1,%2};" : "=l"(r) : "f"(a), "f"(b)); return r;
}
__device__ __forceinline__ void unpack2(ull v, float& a, float& b) {
    asm("mov.b64 {%0,%1}, %2;" : "=f"(a), "=f"(b) : "l"(v));
}
__device__ __forceinline__ void fma2(ull& acc, ull a, ull b) {
    asm("fma.rn.f32x2 %0, %1, %2, %0;" : "+l"(acc) : "l"(a), "l"(b));
}
__device__ __forceinline__ ull add2(ull a, ull b) {
    ull r; asm("add.rn.f32x2 %0, %1, %2;" : "=l"(r) : "l"(a), "l"(b)); return r;
}
__device__ __forceinline__ void lds_v2u64(unsigned addr, ull& x, ull& y) {
    asm volatile("ld.shared.v2.u64 {%0,%1}, [%2];" : "=l"(x), "=l"(y) : "r"(addr));
}

// one forward step for this thread's column: dot(p, expT[:,c]) -> renorm -> *exp(em)
#define CRF_STEP(E, REN) do {                                               \
    unsigned pa_ = pbase + (unsigned)buf * 256u;                            \
    ull a0_=0, a1_=0, a2_=0, a3_=0;                                         \
    _Pragma("unroll")                                                       \
    for (int k_ = 0; k_ < 14; k_ += 2) {                                    \
        ull x_, y_;                                                         \
        lds_v2u64(pa_ + 16u * k_, x_, y_);                                  \
        fma2(a0_, x_, ep[2*k_]);  fma2(a1_, y_, ep[2*k_+1]);                \
        lds_v2u64(pa_ + 16u * (k_+1), x_, y_);                              \
        fma2(a2_, x_, ep[2*k_+2]); fma2(a3_, y_, ep[2*k_+3]);               \
    }                                                                       \
    float u_, v_;                                                           \
    unpack2(add2(add2(a0_, a2_), add2(a1_, a3_)), u_, v_);                  \
    float dot_ = u_ + v_;                                                   \
    float r_ = 1.0f;                                                        \
    if (REN) {                                                              \
        float s_ = p_row[buf * 64];                                         \
        r_ = __fdividef(1.0f, s_);                                          \
        L += __logf(s_);                                                    \
    }                                                                       \
    float np_ = dot_ * r_ * __expf(E);                                      \
    buf ^= 1;                                                               \
    if (okC) p_row[buf * 64 + cc] = np_;                                    \
    __syncthreads();                                                        \
    pcur = np_;                                                             \
} while (0)

#define LOAD4(P, BASEROW) do {                                              \
    _Pragma("unroll")                                                       \
    for (int j_ = 0; j_ < 4; j_++) {                                        \
        int rr_ = (BASEROW) + j_; if (rr_ > Tn - 1) rr_ = Tn - 1;           \
        P[j_] = __ldg(emb + (size_t)rr_ * Cn + cc);                         \
    }                                                                       \
} while (0)

__global__ void __launch_bounds__(64)
crf_fwd_kernel(const float* __restrict__ em,
               const int*   __restrict__ tags,
               const float* __restrict__ mask,
               const float* __restrict__ trans,
               float* __restrict__ out)
{
    __shared__ float trs[Cn * Cn];
    __shared__ __align__(16) float p_sm[2][64];  // double-buffered scaled probs
    __shared__ float wred[2];
    __shared__ int   slast;

    const int tid  = threadIdx.x;
    const int lane = tid & 31;
    const int w    = tid >> 5;
    const int b    = blockIdx.x;

    for (int i = tid; i < Cn * Cn; i += 64) trs[i] = trans[i];
    // zero-pad both p buffers (slots >= Cn must stay 0 forever)
    p_sm[0][tid] = 0.f;
    p_sm[1][tid] = 0.f;
    __syncthreads();

    const bool okC = (tid < Cn);
    const int  cc  = okC ? tid : (Cn - 1);
    const float* emb = em + (size_t)b * Tn * Cn;
    const int*   tg  = tags + b * Tn;
    float* p_row = &p_sm[0][0];
    const unsigned pbase = (unsigned)__cvta_generic_to_shared(p_row);

    // ---- sequence length = sum(mask), block-wide ----
    float ms = 0.f;
    for (int i = tid; i < Tn; i += 64) ms += mask[b * Tn + i];
#pragma unroll
    for (int off = 16; off; off >>= 1) ms += __shfl_xor_sync(~0u, ms, off);
    if (lane == 0) wred[w] = ms;
    __syncthreads();
    const int tlim = (int)(wred[0] + wred[1]);   // steps for t in [2, tlim)

    // ---- packed exp(transition) column for this thread: ep[k]=(E[2k][c],E[2k+1][c]) ----
    ull ep[28];
#pragma unroll
    for (int k = 0; k < 28; k++) {
        int r0 = 2 * k, r1 = 2 * k + 1;
        float v0 = (r0 < Cn) ? __expf(trs[r0 * Cn + cc]) : 0.f;
        float v1 = (r1 < Cn) ? __expf(trs[r1 * Cn + cc]) : 0.f;
        ep[k] = pack2(v0, v1);
    }

    // ---- init: p = exp(T[BOS,c] + em[b,1,c]) ----
    float pcur = __expf(trs[BOSi * Cn + cc] + emb[Cn + cc]);
    int buf = 0;
    if (okC) p_row[cc] = pcur;
    __syncthreads();

    float L = 0.f;
    float eA[4], eB[4];

    LOAD4(eA, 2);
    int base = 2;
    for (;;) {
        if (base + 4 > tlim) break;
        LOAD4(eB, base + 4);
        CRF_STEP(eA[0], true);
        CRF_STEP(eA[1], false);
        CRF_STEP(eA[2], false);
        CRF_STEP(eA[3], false);
        base += 4;
        if (base + 4 > tlim) break;
        LOAD4(eA, base + 4);
        CRF_STEP(eB[0], true);
        CRF_STEP(eB[1], false);
        CRF_STEP(eB[2], false);
        CRF_STEP(eB[3], false);
        base += 4;
    }
    for (int t = base; t < tlim; t++) {          // scalar tail (< 4 steps)
        float e = __ldg(emb + (size_t)t * Cn + cc);
        CRF_STEP(e, false);
    }

    // ---- partition = L + log( sum_c p_c * exp(T[c,EOS]) ) ----
    float f = okC ? pcur * __expf(trs[cc * Cn + EOSi]) : 0.f;
#pragma unroll
    for (int off = 16; off; off >>= 1) f += __shfl_xor_sync(~0u, f, off);
    if (lane == 0) wred[w] = f;
    __syncthreads();
    float partition = L + __logf(wred[0] + wred[1]);

    // ---- gold-path score ----
    float s = 0.f;
    for (int t = 2 + tid; t < tlim; t += 64) {
        int a = tg[t - 1], c = tg[t];
        s += emb[(size_t)t * Cn + c] + trs[a * Cn + c];
    }
#pragma unroll
    for (int off = 16; off; off >>= 1) s += __shfl_xor_sync(~0u, s, off);
    __syncthreads();   // wred reuse hazard
    if (lane == 0) wred[w] = s;
    __syncthreads();

    if (tid == 0) {
        float s_tot = wred[0] + wred[1];
        int   t1    = tg[1];
        float first = trs[BOSi * Cn + t1] + emb[Cn + t1];
        int   lt    = tg[tlim];
        float score = first + s_tot + trs[lt * Cn + EOSi];
        g_partial[b] = partition - score;
    }

    // ---- fused reduction: last block sums all partials ----
    __threadfence();
    __syncthreads();
    if (tid == 0) {
        unsigned tk = atomicAdd(&g_ticket, 1u);
        slast = (tk == (unsigned)(gridDim.x - 1)) ? 1 : 0;
    }
    __syncthreads();
    if (slast) {
        __threadfence();
        float acc = 0.f;
        for (int i = tid; i < Bn; i += 64) acc += __ldcg(&g_partial[i]);
#pragma unroll
        for (int off = 16; off; off >>= 1) acc += __shfl_xor_sync(~0u, acc, off);
        if (lane == 0) wred[w] = acc;
        __syncthreads();
        if (tid == 0) {
            out[0] = wred[0] + wred[1];
            g_ticket = 0;   // reset for next graph replay
        }
    }
}

extern "C" void kernel_launch(void* const* d_in, const int* in_sizes, int n_in,
                              void* d_out, int out_size)
{
    const float* em    = (const float*)d_in[0];
    const int*   tags  = (const int*)  d_in[1];
    const float* mask  = (const float*)d_in[2];
    const float* trans = (const float*)d_in[3];
    float* out = (float*)d_out;

    crf_fwd_kernel<<<Bn, 64>>>(em, tags, mask, trans, out);
}